// round 12
// baseline (speedup 1.0000x reference)
#include <cuda_runtime.h>
#include <math.h>
#include <stdint.h>

// ---------------------------------------------------------------------------
// FedTGPClientLoss:
//   ce    = mean_b [ logsumexp(logits[b,:]) - logits[b, label_b] ]   (0 if !finite)
//   proto = mean_b mean_d (features[b,d] - protos[label_b, d])^2
//   total = ce + proto                                               (ce if !finite)
// Output: [total, ce, proto]  (3 x f32)
//
// Two warps per row (each owns half the logits + half of D). Halved register
// footprint (v[4] instead of v[8]) buys 75% occupancy WITH batched loads --
// the quadrant no prior variant reached. Single-pass sum-of-exp so the two
// half-row partials combine by plain addition (one smem exchange per 4-row
// block). Warp-uniform two-pass fallback for |logit|>~88 in the combine warp.
// Fused grid reduction via threadfence pattern.
// ---------------------------------------------------------------------------

#define MAXBLK 8192
__device__ double   g_pce[MAXBLK];
__device__ double   g_pms[MAXBLK];
__device__ unsigned g_count = 0;   // reset by the last block each call

#define NEG_INF (-__int_as_float(0x7f800000))

__global__ __launch_bounds__(256, 6) void row_kernel(
    const float* __restrict__ logits,
    const int*   __restrict__ l32,     // labels viewed as int32 words
    const float* __restrict__ features,
    const float* __restrict__ protos,
    float* __restrict__ out,
    int B, int C, int D)
{
    const int lane = threadIdx.x & 31;
    const int wid  = threadIdx.x >> 5;     // 0..7
    const int pair = wid >> 1;             // 0..3  (row within block)
    const int half = wid & 1;              // 0 = front half, 1 = back half
    const int row  = blockIdx.x * 4 + pair;

    // ---- per-warp label dtype detection (first 64 int32 words) ----
    // int64 labels < C  =>  all odd (high) words are 0.
    // int32 labels uniform [0,C)  =>  P(32 odd words all zero) ~ C^-32 ~ 0.
    int pidx = 2 * lane + 1;
    int probe = (pidx < B) ? l32[pidx] : 0;
    const bool lbl64 = (__ballot_sync(0xFFFFFFFFu, probe != 0) == 0u);

    const int C4 = C >> 2, Ctail = C & 3, D4 = D >> 2;
    const bool fast = (C4 <= 256) && (Ctail == 0) && (D4 == 128);

    __shared__ float s_s[8], s_q[8];       // per-warp half-row partials
    __shared__ float s_ce[4], s_ms[4];     // generic-path per-row results
    __shared__ bool  s_is_last;

    float s = 0.0f, sq = 0.0f;

    if (fast && row < B) {
        const int label = lbl64 ? l32[2 * row] : l32[row];
        const float4* lrow = (const float4*)(logits + (size_t)row * C);

        // ---- batched half-row logits loads: 4 x LDG.128 per lane ----
        const int cbase = half * 128;
        float4 v[4];
        #pragma unroll
        for (int j = 0; j < 4; j++) {
            int idx = cbase + j * 32 + lane;
            v[j] = (idx < C4) ? lrow[idx]
                              : make_float4(NEG_INF, NEG_INF, NEG_INF, NEG_INF);
        }

        // exps: 4 independent accumulator chains
        float s0 = 0.f, s1 = 0.f, s2 = 0.f, s3 = 0.f;
        #pragma unroll
        for (int j = 0; j < 4; j++) {
            s0 += __expf(v[j].x);
            s1 += __expf(v[j].y);
            s2 += __expf(v[j].z);
            s3 += __expf(v[j].w);
        }
        s = (s0 + s1) + (s2 + s3);

        // ---- batched half-D feature/proto loads: 2+2 x LDG.128 per lane ----
        const float4* frow = (const float4*)(features + (size_t)row   * D);
        const float4* prow = (const float4*)(protos   + (size_t)label * D);
        const int dbase = half * 64;
        float4 f[2], p[2];
        #pragma unroll
        for (int j = 0; j < 2; j++) {
            f[j] = frow[dbase + j * 32 + lane];
            p[j] = prow[dbase + j * 32 + lane];
        }
        #pragma unroll
        for (int j = 0; j < 2; j++) {
            float dx = f[j].x - p[j].x, dy = f[j].y - p[j].y;
            float dz = f[j].z - p[j].z, dw = f[j].w - p[j].w;
            sq = fmaf(dx, dx, fmaf(dy, dy, fmaf(dz, dz, fmaf(dw, dw, sq))));
        }

        // ---- warp sum reductions ----
        #pragma unroll
        for (int off = 16; off > 0; off >>= 1) {
            s  += __shfl_xor_sync(0xFFFFFFFFu, s,  off);
            sq += __shfl_xor_sync(0xFFFFFFFFu, sq, off);
        }
    } else if (!fast && row < B && half == 0) {
        // ================= generic path: one warp per row ==================
        const int label = lbl64 ? l32[2 * row] : l32[row];
        const float* lr = logits + (size_t)row * C;
        const float4* lrow = (const float4*)lr;
        const float lbl_logit = __ldg(lr + label);

        float ss = 0.0f;
        for (int idx = lane; idx < C4; idx += 32) {
            float4 q = lrow[idx];
            ss += __expf(q.x) + __expf(q.y) + __expf(q.z) + __expf(q.w);
        }
        if (lane < Ctail) ss += __expf(lr[C4 * 4 + lane]);

        const float4* frow = (const float4*)(features + (size_t)row   * D);
        const float4* prow = (const float4*)(protos   + (size_t)label * D);
        float qq = 0.0f;
        for (int idx = lane; idx < D4; idx += 32) {
            float4 ff = frow[idx];
            float4 pp = prow[idx];
            float dx = ff.x - pp.x, dy = ff.y - pp.y;
            float dz = ff.z - pp.z, dw = ff.w - pp.w;
            qq = fmaf(dx, dx, fmaf(dy, dy, fmaf(dz, dz, fmaf(dw, dw, qq))));
        }
        const int Dtail = D & 3;
        if (lane < Dtail) {
            float d = features[(size_t)row * D + D4 * 4 + lane]
                    - protos[(size_t)label * D + D4 * 4 + lane];
            qq = fmaf(d, d, qq);
        }

        #pragma unroll
        for (int off = 16; off > 0; off >>= 1) {
            ss += __shfl_xor_sync(0xFFFFFFFFu, ss, off);
            qq += __shfl_xor_sync(0xFFFFFFFFu, qq, off);
        }

        float lse;
        if (__builtin_expect(isinf(ss) || !(ss > 0.0f), 0)) {
            float m = NEG_INF;
            for (int idx = lane; idx < C4; idx += 32) {
                float4 q = lrow[idx];
                m = fmaxf(m, fmaxf(fmaxf(q.x, q.y), fmaxf(q.z, q.w)));
            }
            if (lane < Ctail) m = fmaxf(m, lr[C4 * 4 + lane]);
            #pragma unroll
            for (int off = 16; off > 0; off >>= 1)
                m = fmaxf(m, __shfl_xor_sync(0xFFFFFFFFu, m, off));
            float t = 0.0f;
            for (int idx = lane; idx < C4; idx += 32) {
                float4 q = lrow[idx];
                t += __expf(q.x - m) + __expf(q.y - m)
                   + __expf(q.z - m) + __expf(q.w - m);
            }
            if (lane < Ctail) t += __expf(lr[C4 * 4 + lane] - m);
            #pragma unroll
            for (int off = 16; off > 0; off >>= 1)
                t += __shfl_xor_sync(0xFFFFFFFFu, t, off);
            lse = m + __logf(t);
        } else {
            lse = __logf(ss);
        }
        if (lane == 0) {
            s_ce[pair] = lse - lbl_logit;
            s_ms[pair] = qq / (float)D;
        }
    }

    if (lane == 0) { s_s[wid] = s; s_q[wid] = sq; }
    __syncthreads();

    // ---- warp 0: combine half-row partials, handle fallback, emit block partial
    if (wid == 0) {
        const int rr = blockIdx.x * 4 + lane;        // lane 0..3 own rows
        const bool valid = (lane < 4) && (rr < B);

        float ce_r = 0.0f, ms_r = 0.0f;
        float sTot = 0.0f;
        if (valid && fast) {
            sTot = s_s[2 * lane] + s_s[2 * lane + 1];
            float qTot = s_q[2 * lane] + s_q[2 * lane + 1];
            ms_r = qTot / (float)D;
        }
        bool bad = valid && fast && (isinf(sTot) || !(sTot > 0.0f));
        unsigned badmask = __ballot_sync(0xFFFFFFFFu, bad);

        if (valid && fast && !bad) {
            int lb = lbl64 ? l32[2 * rr] : l32[rr];
            float ll = __ldg(logits + (size_t)rr * C + lb);
            ce_r = __logf(sTot) - ll;
        }
        if (valid && !fast) { ce_r = s_ce[lane]; ms_r = s_ms[lane]; }

        // rare fallback: warp-cooperative two-pass logsumexp per flagged row
        while (badmask) {
            int r = __ffs(badmask) - 1; badmask &= badmask - 1;
            int rb = blockIdx.x * 4 + r;
            int lb = lbl64 ? l32[2 * rb] : l32[rb];
            const float* lr = logits + (size_t)rb * C;
            const float4* lrow = (const float4*)lr;
            float m = NEG_INF;
            for (int idx = lane; idx < C4; idx += 32) {
                float4 q = lrow[idx];
                m = fmaxf(m, fmaxf(fmaxf(q.x, q.y), fmaxf(q.z, q.w)));
            }
            #pragma unroll
            for (int off = 16; off > 0; off >>= 1)
                m = fmaxf(m, __shfl_xor_sync(0xFFFFFFFFu, m, off));
            float t = 0.0f;
            for (int idx = lane; idx < C4; idx += 32) {
                float4 q = lrow[idx];
                t += __expf(q.x - m) + __expf(q.y - m)
                   + __expf(q.z - m) + __expf(q.w - m);
            }
            #pragma unroll
            for (int off = 16; off > 0; off >>= 1)
                t += __shfl_xor_sync(0xFFFFFFFFu, t, off);
            float lse = m + __logf(t);
            float ll  = __ldg(lr + lb);
            if (lane == r) ce_r = lse - ll;
        }

        // sum the (<=4) per-row results across the warp
        float bce = ce_r, bms = ms_r;
        #pragma unroll
        for (int off = 16; off > 0; off >>= 1) {
            bce += __shfl_xor_sync(0xFFFFFFFFu, bce, off);
            bms += __shfl_xor_sync(0xFFFFFFFFu, bms, off);
        }

        if (lane == 0) {
            g_pce[blockIdx.x] = (double)bce;
            g_pms[blockIdx.x] = (double)bms;
            __threadfence();
            unsigned prev = atomicAdd(&g_count, 1u);
            s_is_last = (prev == gridDim.x - 1);
        }
    }
    __syncthreads();

    // ---- last-arriving block: reduce L2-hot partials, emit outputs ----
    if (s_is_last) {
        const int tid = threadIdx.x;
        const int nb  = gridDim.x;
        double ce = 0.0, ms = 0.0;
        for (int i = tid; i < nb; i += 256) { ce += g_pce[i]; ms += g_pms[i]; }

        __shared__ double red[512];
        red[tid] = ce; red[256 + tid] = ms;
        __syncthreads();
        #pragma unroll
        for (int off = 128; off > 0; off >>= 1) {
            if (tid < off) {
                red[tid]       += red[tid + off];
                red[256 + tid] += red[256 + tid + off];
            }
            __syncthreads();
        }

        if (tid == 0) {
            float ce_loss = (float)(red[0] / (double)B);
            if (!isfinite(ce_loss)) ce_loss = 0.0f;
            float proto_loss = (float)(red[256] / (double)B);
            float total = ce_loss + proto_loss;
            if (!isfinite(total)) total = ce_loss;
            out[0] = total;
            out[1] = ce_loss;
            out[2] = proto_loss;
            g_count = 0;          // reset for next graph replay
        }
    }
}

extern "C" void kernel_launch(void* const* d_in, const int* in_sizes, int n_in,
                              void* d_out, int out_size) {
    const float* logits   = (const float*)d_in[0];
    const int*   labels   = (const int*)d_in[1];
    const float* features = (const float*)d_in[2];
    const float* protos   = (const float*)d_in[3];
    float* out = (float*)d_out;

    const int B = in_sizes[1];                 // 16384
    const int C = in_sizes[0] / B;             // 1000
    const int D = in_sizes[2] / B;             // 512

    const int blocks = (B + 3) / 4;            // 4 rows per block (2 warps/row)
    row_kernel<<<blocks, 256>>>(logits, labels, features, protos, out, B, C, D);
}

// round 13
// speedup vs baseline: 1.0681x; 1.0681x over previous
#include <cuda_runtime.h>
#include <math.h>
#include <stdint.h>

// ---------------------------------------------------------------------------
// FedTGPClientLoss:
//   ce    = mean_b [ logsumexp(logits[b,:]) - logits[b, label_b] ]   (0 if !finite)
//   proto = mean_b mean_d (features[b,d] - protos[label_b, d])^2
//   total = ce + proto                                               (ce if !finite)
// Output: [total, ce, proto]  (3 x f32)
//
// Exact layout of the 25.1us winner (one warp per row, batched v[8] loads,
// fused threadfence grid reduction) with the max pass deleted: single-pass
// sum-of-exp (exact and overflow-free for |logit| < 88), so exps start as
// loads land and the shuffle-max round trip disappears. Warp-uniform
// two-pass max-subtracted fallback for extreme inputs (never taken here).
// ---------------------------------------------------------------------------

#define MAXBLK 8192
__device__ double   g_pce[MAXBLK];
__device__ double   g_pms[MAXBLK];
__device__ unsigned g_count = 0;   // reset by the last block each call

#define NEG_INF (-__int_as_float(0x7f800000))

__global__ __launch_bounds__(256) void row_kernel(
    const float* __restrict__ logits,
    const int*   __restrict__ l32,     // labels viewed as int32 words
    const float* __restrict__ features,
    const float* __restrict__ protos,
    float* __restrict__ out,
    int B, int C, int D)
{
    const int lane = threadIdx.x & 31;
    const int wid  = threadIdx.x >> 5;
    const int row  = blockIdx.x * 8 + wid;
    const bool active = (row < B);

    float ce_f = 0.0f, ms_f = 0.0f;

    if (active) {
        // ---- per-warp label dtype detection (first 64 int32 words = 256B) ----
        // int64 labels < C  =>  all odd (high) words are 0.
        // int32 labels uniform [0,C)  =>  P(32 odd words all zero) ~ C^-32 ~ 0.
        int probe = l32[2 * lane + 1];
        bool lbl64 = (__ballot_sync(0xFFFFFFFFu, probe != 0) == 0u);
        const int label = lbl64 ? l32[2 * row] : l32[row];

        const float* lr = logits + (size_t)row * C;
        const float4* lrow = (const float4*)lr;
        const int C4 = C >> 2;
        const int Ctail = C & 3;
        const int D4 = D >> 2;

        float s = 0.0f, sq = 0.0f;
        float lbl_logit;

        if (C4 <= 256 && Ctail == 0 && D4 == 128) {
            // ============ fast path: batched loads, single-pass exp ========
            // 1) batch-issue 8 logits float4 loads (MLP 8)
            float4 v[8];
            #pragma unroll
            for (int j = 0; j < 8; j++) {
                int idx = j * 32 + lane;
                v[j] = (idx < C4) ? lrow[idx]
                                  : make_float4(NEG_INF, NEG_INF, NEG_INF, NEG_INF);
            }

            // 2) batch-issue feature/proto loads (consumed after the exps)
            const float4* frow = (const float4*)(features + (size_t)row   * D);
            const float4* prow = (const float4*)(protos   + (size_t)label * D);
            float4 f[4], p[4];
            #pragma unroll
            for (int j = 0; j < 4; j++) {
                f[j] = frow[j * 32 + lane];
                p[j] = prow[j * 32 + lane];
            }
            lbl_logit = __ldg(lr + label);     // lines just fetched -> L1 hit

            // 3) exps as loads land: 4 independent accumulator chains
            float s0 = 0.f, s1 = 0.f, s2 = 0.f, s3 = 0.f;
            #pragma unroll
            for (int j = 0; j < 8; j++) {
                s0 += __expf(v[j].x);
                s1 += __expf(v[j].y);
                s2 += __expf(v[j].z);
                s3 += __expf(v[j].w);
            }
            s = (s0 + s1) + (s2 + s3);         // exp(-inf)=0 pads

            // 4) MSE FMAs
            #pragma unroll
            for (int j = 0; j < 4; j++) {
                float dx = f[j].x - p[j].x, dy = f[j].y - p[j].y;
                float dz = f[j].z - p[j].z, dw = f[j].w - p[j].w;
                sq = fmaf(dx, dx, fmaf(dy, dy, fmaf(dz, dz, fmaf(dw, dw, sq))));
            }
        } else {
            // ============ generic path ============
            lbl_logit = __ldg(lr + label);
            for (int idx = lane; idx < C4; idx += 32) {
                float4 q = lrow[idx];
                s += __expf(q.x) + __expf(q.y) + __expf(q.z) + __expf(q.w);
            }
            if (lane < Ctail) s += __expf(lr[C4 * 4 + lane]);

            const float4* frow = (const float4*)(features + (size_t)row   * D);
            const float4* prow = (const float4*)(protos   + (size_t)label * D);
            for (int idx = lane; idx < D4; idx += 32) {
                float4 ff = frow[idx];
                float4 pp = prow[idx];
                float dx = ff.x - pp.x, dy = ff.y - pp.y;
                float dz = ff.z - pp.z, dw = ff.w - pp.w;
                sq = fmaf(dx, dx, fmaf(dy, dy, fmaf(dz, dz, fmaf(dw, dw, sq))));
            }
            const int Dtail = D & 3;
            if (lane < Dtail) {
                float d = features[(size_t)row * D + D4 * 4 + lane]
                        - protos[(size_t)label * D + D4 * 4 + lane];
                sq = fmaf(d, d, sq);
            }
        }

        // ---- warp sum reductions (s, sq interleaved -> latency overlaps) ----
        #pragma unroll
        for (int off = 16; off > 0; off >>= 1) {
            s  += __shfl_xor_sync(0xFFFFFFFFu, s,  off);
            sq += __shfl_xor_sync(0xFFFFFFFFu, sq, off);
        }

        float lse;
        if (__builtin_expect(isinf(s) || !(s > 0.0f), 0)) {
            // rare fallback: classic two-pass max-subtracted logsumexp
            // (taken only if some |logit| >~ 88; reloads are cache-hot)
            float m = NEG_INF;
            for (int idx = lane; idx < C4; idx += 32) {
                float4 q = lrow[idx];
                m = fmaxf(m, fmaxf(fmaxf(q.x, q.y), fmaxf(q.z, q.w)));
            }
            if (lane < Ctail) m = fmaxf(m, lr[C4 * 4 + lane]);
            #pragma unroll
            for (int off = 16; off > 0; off >>= 1)
                m = fmaxf(m, __shfl_xor_sync(0xFFFFFFFFu, m, off));
            float t = 0.0f;
            for (int idx = lane; idx < C4; idx += 32) {
                float4 q = lrow[idx];
                t += __expf(q.x - m) + __expf(q.y - m)
                   + __expf(q.z - m) + __expf(q.w - m);
            }
            if (lane < Ctail) t += __expf(lr[C4 * 4 + lane] - m);
            #pragma unroll
            for (int off = 16; off > 0; off >>= 1)
                t += __shfl_xor_sync(0xFFFFFFFFu, t, off);
            lse = m + __logf(t);
        } else {
            lse = __logf(s);
        }

        ce_f = lse - lbl_logit;
        ms_f = sq / (float)D;
    }

    // ---- block reduction of the 8 warp results (doubles) ----
    __shared__ double sm_ce[8], sm_ms[8];
    __shared__ bool   s_is_last;
    if (lane == 0) { sm_ce[wid] = (double)ce_f; sm_ms[wid] = (double)ms_f; }
    __syncthreads();

    if (threadIdx.x == 0) {
        double bce = 0.0, bms = 0.0;
        #pragma unroll
        for (int j = 0; j < 8; j++) { bce += sm_ce[j]; bms += sm_ms[j]; }
        g_pce[blockIdx.x] = bce;
        g_pms[blockIdx.x] = bms;
        __threadfence();
        unsigned prev = atomicAdd(&g_count, 1u);
        s_is_last = (prev == gridDim.x - 1);
    }
    __syncthreads();

    // ---- last-arriving block: reduce L2-hot partials, emit outputs ----
    if (s_is_last) {
        const int tid = threadIdx.x;
        const int nb  = gridDim.x;
        double ce = 0.0, ms = 0.0;
        for (int i = tid; i < nb; i += 256) { ce += g_pce[i]; ms += g_pms[i]; }

        __shared__ double red[512];
        red[tid] = ce; red[256 + tid] = ms;
        __syncthreads();
        #pragma unroll
        for (int off = 128; off > 0; off >>= 1) {
            if (tid < off) {
                red[tid]       += red[tid + off];
                red[256 + tid] += red[256 + tid + off];
            }
            __syncthreads();
        }

        if (tid == 0) {
            float ce_loss = (float)(red[0] / (double)B);
            if (!isfinite(ce_loss)) ce_loss = 0.0f;
            float proto_loss = (float)(red[256] / (double)B);
            float total = ce_loss + proto_loss;
            if (!isfinite(total)) total = ce_loss;
            out[0] = total;
            out[1] = ce_loss;
            out[2] = proto_loss;
            g_count = 0;          // reset for next graph replay
        }
    }
}

extern "C" void kernel_launch(void* const* d_in, const int* in_sizes, int n_in,
                              void* d_out, int out_size) {
    const float* logits   = (const float*)d_in[0];
    const int*   labels   = (const int*)d_in[1];
    const float* features = (const float*)d_in[2];
    const float* protos   = (const float*)d_in[3];
    float* out = (float*)d_out;

    const int B = in_sizes[1];                 // 16384
    const int C = in_sizes[0] / B;             // 1000
    const int D = in_sizes[2] / B;             // 512

    const int blocks = (B + 7) / 8;            // one warp per row, 8 warps/block
    row_kernel<<<blocks, 256>>>(logits, labels, features, protos, out, B, C, D);
}